// round 13
// baseline (speedup 1.0000x reference)
#include <cuda_runtime.h>
#include <cuda_bf16.h>
#include <math.h>
#include <float.h>

#define BT 2048
#define DMODEL 1024
#define S0 2048
#define S1 1024
#define S2 512
#define STOT 3584
#define KSPLIT 3072   // A:[hi|lo|hi]  B:[hi|hi|lo]
#define BAND_EPS 1e-5f

// ---- static device scratch (no allocation allowed) ----
__device__ float g_h[BT * DMODEL];
__device__ float g_scores[BT * STOT];
__device__ float g_route[BT * 3];
__device__ int   g_dynk[BT];
__device__ __nv_bfloat16 g_A2[(size_t)BT * KSPLIT];     // split q (shared by both GEMMs)
__device__ __nv_bfloat16 g_B2[(size_t)STOT * KSPLIT];   // split K banks
__device__ __nv_bfloat16 g_B2h[(size_t)DMODEL * KSPLIT];// split rW1^T

__device__ __forceinline__ float gelu_erf(float x) {
    return 0.5f * x * (1.0f + erff(x * 0.70710678118654752f));
}
__device__ __forceinline__ unsigned f2key(float f) {
    unsigned b = __float_as_uint(f);
    return (b & 0x80000000u) ? ~b : (b | 0x80000000u);
}
__device__ __forceinline__ float key2f(unsigned u) {
    unsigned b = (u & 0x80000000u) ? (u ^ 0x80000000u) : ~u;
    return __uint_as_float(b);
}

// ============================================================================
// Split kernels: fp32 -> (hi, lo) bf16 along K for 3-product GEMM.
// ============================================================================
__global__ void split_q_kernel(const float* __restrict__ q) {
    int p = blockIdx.x * 256 + threadIdx.x;
    int m = p >> 9, j = p & 511;
    float2 v = *(const float2*)&q[((size_t)m << 10) + (j << 1)];
    __nv_bfloat16 h0 = __float2bfloat16(v.x);
    __nv_bfloat16 h1 = __float2bfloat16(v.y);
    __nv_bfloat16 l0 = __float2bfloat16(v.x - __bfloat162float(h0));
    __nv_bfloat16 l1 = __float2bfloat16(v.y - __bfloat162float(h1));
    __nv_bfloat162 hh; hh.x = h0; hh.y = h1;
    __nv_bfloat162 ll; ll.x = l0; ll.y = l1;
    size_t base = (size_t)m * KSPLIT + (j << 1);
    *(__nv_bfloat162*)&g_A2[base       ] = hh;   // hi
    *(__nv_bfloat162*)&g_A2[base + 1024] = ll;   // lo
    *(__nv_bfloat162*)&g_A2[base + 2048] = hh;   // hi
}

__global__ void split_k_kernel(const float* __restrict__ K0p,
                               const float* __restrict__ K1p,
                               const float* __restrict__ K2p) {
    int p = blockIdx.x * 256 + threadIdx.x;
    int s = p >> 9, j = p & 511;
    const float* src;
    int r;
    if (s < S0)           { src = K0p; r = s; }
    else if (s < S0 + S1) { src = K1p; r = s - S0; }
    else                  { src = K2p; r = s - S0 - S1; }
    float2 v = *(const float2*)&src[((size_t)r << 10) + (j << 1)];
    __nv_bfloat16 h0 = __float2bfloat16(v.x);
    __nv_bfloat16 h1 = __float2bfloat16(v.y);
    __nv_bfloat16 l0 = __float2bfloat16(v.x - __bfloat162float(h0));
    __nv_bfloat16 l1 = __float2bfloat16(v.y - __bfloat162float(h1));
    __nv_bfloat162 hh; hh.x = h0; hh.y = h1;
    __nv_bfloat162 ll; ll.x = l0; ll.y = l1;
    size_t base = (size_t)s * KSPLIT + (j << 1);
    *(__nv_bfloat162*)&g_B2[base       ] = hh;   // hi
    *(__nv_bfloat162*)&g_B2[base + 1024] = hh;   // hi
    *(__nv_bfloat162*)&g_B2[base + 2048] = ll;   // lo
}

// Transposing split of rW1: g_B2h[n][k-split] from rW1[k][n].
__global__ void split_w1_kernel(const float* __restrict__ rW1) {
    int p = blockIdx.x * 256 + threadIdx.x;
    int n  = p & 1023;
    int kp = p >> 10;
    float v0 = rW1[(size_t)(2 * kp    ) * DMODEL + n];
    float v1 = rW1[(size_t)(2 * kp + 1) * DMODEL + n];
    __nv_bfloat16 h0 = __float2bfloat16(v0);
    __nv_bfloat16 h1 = __float2bfloat16(v1);
    __nv_bfloat16 l0 = __float2bfloat16(v0 - __bfloat162float(h0));
    __nv_bfloat16 l1 = __float2bfloat16(v1 - __bfloat162float(h1));
    __nv_bfloat162 hh; hh.x = h0; hh.y = h1;
    __nv_bfloat162 ll; ll.x = l0; ll.y = l1;
    size_t base = (size_t)n * KSPLIT + (kp << 1);
    *(__nv_bfloat162*)&g_B2h[base       ] = hh;  // hi
    *(__nv_bfloat162*)&g_B2h[base + 1024] = hh;  // hi
    *(__nv_bfloat162*)&g_B2h[base + 2048] = ll;  // lo
}

// ============================================================================
// bf16 HMMA GEMM core. 128x128 block tile, K-chunk 32, 4 warps (2x2),
// warp tile 64x64, m16n8k16, ldmatrix fragment fetch, 128 threads.
// ============================================================================
#define LDAS 40

__device__ __forceinline__ void mma16816(float* c, const unsigned* a, const unsigned* b) {
    asm volatile(
        "mma.sync.aligned.m16n8k16.row.col.f32.bf16.bf16.f32 "
        "{%0,%1,%2,%3}, {%4,%5,%6,%7}, {%8,%9}, {%0,%1,%2,%3};\n"
        : "+f"(c[0]), "+f"(c[1]), "+f"(c[2]), "+f"(c[3])
        : "r"(a[0]), "r"(a[1]), "r"(a[2]), "r"(a[3]), "r"(b[0]), "r"(b[1]));
}

__device__ __forceinline__ void ldmx4(unsigned& r0, unsigned& r1,
                                      unsigned& r2, unsigned& r3, unsigned addr) {
    asm volatile(
        "ldmatrix.sync.aligned.m8n8.x4.shared.b16 {%0,%1,%2,%3}, [%4];\n"
        : "=r"(r0), "=r"(r1), "=r"(r2), "=r"(r3) : "r"(addr));
}

// Shared mainloop: fills c[4][8][4] from g_A2 row-block m0 and Bsrc row-block n0.
// 128 threads, warps as 2x2: warp_m = wid>>1 (64 rows), warp_n = wid&1 (64 cols).
__device__ __forceinline__ void mma_mainloop(const __nv_bfloat16* __restrict__ Bsrc,
                                             int m0, int n0, int tid,
                                             __nv_bfloat16* As, __nv_bfloat16* Bs,
                                             float c[4][8][4]) {
    const int wid = tid >> 5, lane = tid & 31;
    const int warp_m = wid >> 1;
    const int warp_n = wid & 1;
    const int lrow = tid;                    // each thread owns one row

    const __nv_bfloat16* Aptr = g_A2 + (size_t)(m0 + lrow) * KSPLIT;
    const __nv_bfloat16* Bptr = Bsrc + (size_t)(n0 + lrow) * KSPLIT;
    __nv_bfloat16* AsW = As + lrow * LDAS;
    __nv_bfloat16* BsW = Bs + lrow * LDAS;

    // ldmatrix lane address components (validated mapping, R12):
    const unsigned AsBase = (unsigned)__cvta_generic_to_shared(As);
    const unsigned BsBase = (unsigned)__cvta_generic_to_shared(Bs);
    const int rowA = warp_m * 64 + (lane & 15);
    const int colA = (lane >> 4) << 3;
    const int rowB = warp_n * 64 + ((lane >> 4) << 3) + (lane & 7);
    const int colB = ((lane >> 3) & 1) << 3;

    // register prefetch: full 32-elem row per thread for A and B (4 float4 each)
    float4 ap[4], bp[4];
    #pragma unroll
    for (int j = 0; j < 4; j++) {
        ap[j] = *(const float4*)(Aptr + j * 8);
        bp[j] = *(const float4*)(Bptr + j * 8);
    }

    for (int kt = 0; kt < KSPLIT / 32; kt++) {
        #pragma unroll
        for (int j = 0; j < 4; j++) {
            *(float4*)(AsW + j * 8) = ap[j];
            *(float4*)(BsW + j * 8) = bp[j];
        }
        __syncthreads();
        if (kt < KSPLIT / 32 - 1) {
            const int ko = (kt + 1) * 32;
            #pragma unroll
            for (int j = 0; j < 4; j++) {
                ap[j] = *(const float4*)(Aptr + ko + j * 8);
                bp[j] = *(const float4*)(Bptr + ko + j * 8);
            }
        }
        #pragma unroll
        for (int ks = 0; ks < 2; ks++) {
            unsigned a[4][4], b[8][2];
            const unsigned aaddr = AsBase + (unsigned)((rowA * LDAS + ks * 16 + colA) * 2);
            #pragma unroll
            for (int mi = 0; mi < 4; mi++)
                ldmx4(a[mi][0], a[mi][1], a[mi][2], a[mi][3],
                      aaddr + (unsigned)(mi * 16 * LDAS * 2));
            const unsigned baddr = BsBase + (unsigned)((rowB * LDAS + ks * 16 + colB) * 2);
            #pragma unroll
            for (int nj = 0; nj < 4; nj++)
                ldmx4(b[2 * nj][0], b[2 * nj][1], b[2 * nj + 1][0], b[2 * nj + 1][1],
                      baddr + (unsigned)(nj * 16 * LDAS * 2));
            #pragma unroll
            for (int mi = 0; mi < 4; mi++)
                #pragma unroll
                for (int ni = 0; ni < 8; ni++)
                    mma16816(c[mi][ni], a[mi], b[ni]);
        }
        __syncthreads();
    }
}

// ---- scores: g_scores = (A2 @ B2^T)*scale + sal ----
__global__ __launch_bounds__(128, 2)
void scores_mma_kernel(const float* __restrict__ sal0,
                       const float* __restrict__ sal1,
                       const float* __restrict__ sal2) {
    __shared__ __nv_bfloat16 As[128 * LDAS];
    __shared__ __nv_bfloat16 Bs[128 * LDAS];
    const int tid = threadIdx.x;
    const int wid = tid >> 5, lane = tid & 31;
    const int grp = lane >> 2, thr = lane & 3;
    const int warp_m = wid >> 1, warp_n = wid & 1;
    const int m0 = blockIdx.y * 128;
    const int nt = blockIdx.x;

    float c[4][8][4] = {};
    mma_mainloop(g_B2, m0, nt * 128, tid, As, Bs, c);

    const float scale = 0.03125f;
    const float* salp; int sbase;
    if (nt < 16)      { salp = sal0; sbase = 0; }
    else if (nt < 24) { salp = sal1; sbase = S0; }
    else              { salp = sal2; sbase = S0 + S1; }

    #pragma unroll
    for (int mi = 0; mi < 4; mi++) {
        const int r = m0 + warp_m * 64 + mi * 16 + grp;
        #pragma unroll
        for (int ni = 0; ni < 8; ni++) {
            const int cc = nt * 128 + warp_n * 64 + ni * 8 + thr * 2;
            const float s0 = salp[cc - sbase];
            const float s1 = salp[cc + 1 - sbase];
            float2 w0, w1;
            w0.x = c[mi][ni][0] * scale + s0;
            w0.y = c[mi][ni][1] * scale + s1;
            w1.x = c[mi][ni][2] * scale + s0;
            w1.y = c[mi][ni][3] * scale + s1;
            *(float2*)&g_scores[(size_t)r * STOT + cc] = w0;
            *(float2*)&g_scores[(size_t)(r + 8) * STOT + cc] = w1;
        }
    }
}

// ---- hidden: g_h = gelu(A2 @ B2h^T + rb1) ----
__global__ __launch_bounds__(128, 2)
void gemm_h_mma_kernel(const float* __restrict__ bias) {
    __shared__ __nv_bfloat16 As[128 * LDAS];
    __shared__ __nv_bfloat16 Bs[128 * LDAS];
    const int tid = threadIdx.x;
    const int wid = tid >> 5, lane = tid & 31;
    const int grp = lane >> 2, thr = lane & 3;
    const int warp_m = wid >> 1, warp_n = wid & 1;
    const int m0 = blockIdx.y * 128;
    const int n0 = blockIdx.x * 128;

    float c[4][8][4] = {};
    mma_mainloop(g_B2h, m0, n0, tid, As, Bs, c);

    #pragma unroll
    for (int mi = 0; mi < 4; mi++) {
        const int r = m0 + warp_m * 64 + mi * 16 + grp;
        #pragma unroll
        for (int ni = 0; ni < 8; ni++) {
            const int cc = n0 + warp_n * 64 + ni * 8 + thr * 2;
            const float b0 = bias[cc], b1 = bias[cc + 1];
            float2 w0, w1;
            w0.x = gelu_erf(c[mi][ni][0] + b0);
            w0.y = gelu_erf(c[mi][ni][1] + b1);
            w1.x = gelu_erf(c[mi][ni][2] + b0);
            w1.y = gelu_erf(c[mi][ni][3] + b1);
            *(float2*)&g_h[(size_t)r * DMODEL + cc] = w0;
            *(float2*)&g_h[(size_t)(r + 8) * DMODEL + cc] = w1;
        }
    }
}

// ============================================================================
// Route softmax (warp/row) and dyn_k predictor (16 rows/block).
// ============================================================================
__global__ void route_kernel(const float* __restrict__ rW2,
                             const float* __restrict__ rb2) {
    const int row = blockIdx.x * 8 + (threadIdx.x >> 5);
    const int lane = threadIdx.x & 31;
    const float* h = &g_h[(size_t)row * DMODEL];
    float a0 = 0.f, a1 = 0.f, a2 = 0.f;
    for (int d = lane; d < DMODEL; d += 32) {
        float hv = h[d];
        a0 += hv * rW2[d * 3 + 0];
        a1 += hv * rW2[d * 3 + 1];
        a2 += hv * rW2[d * 3 + 2];
    }
    #pragma unroll
    for (int o = 16; o; o >>= 1) {
        a0 += __shfl_xor_sync(0xffffffffu, a0, o);
        a1 += __shfl_xor_sync(0xffffffffu, a1, o);
        a2 += __shfl_xor_sync(0xffffffffu, a2, o);
    }
    if (lane == 0) {
        a0 += rb2[0]; a1 += rb2[1]; a2 += rb2[2];
        float m = fmaxf(a0, fmaxf(a1, a2));
        float e0 = expf(a0 - m), e1 = expf(a1 - m), e2 = expf(a2 - m);
        float inv = 1.0f / (e0 + e1 + e2);
        g_route[row * 3 + 0] = e0 * inv;
        g_route[row * 3 + 1] = e1 * inv;
        g_route[row * 3 + 2] = e2 * inv;
    }
}

__global__ __launch_bounds__(1024)
void pred_kernel(const float* __restrict__ q,
                 const float* __restrict__ pW1,
                 const float* __restrict__ pb1,
                 const float* __restrict__ pW2,
                 const float* __restrict__ pb2) {
    const int tid = threadIdx.x;
    const int r = tid >> 6;
    const int j = tid & 63;
    const int lane = tid & 31;
    const int w = tid >> 5, half = w & 1;
    const int row = blockIdx.x * 16 + r;
    __shared__ float s_part[16][2];

    const float* qr = &q[(size_t)row * DMODEL];
    float acc = 0.f;
    #pragma unroll 8
    for (int d = 0; d < DMODEL; d++)
        acc += qr[d] * pW1[d * 64 + j];
    float val = gelu_erf(acc + pb1[j]) * pW2[j];
    #pragma unroll
    for (int o = 16; o; o >>= 1)
        val += __shfl_xor_sync(0xffffffffu, val, o);
    if (lane == 0) s_part[w >> 1][half] = val;
    __syncthreads();
    if (tid < 16) {
        float s = s_part[tid][0] + s_part[tid][1] + pb2[0];
        float sig = 1.0f / (1.0f + expf(-s));
        int k = (int)floorf(sig * 64.0f);
        g_dynk[blockIdx.x * 16 + tid] = max(1, min(64, k));
    }
}

// ============================================================================
// Fused top-dyn_k (radix select + exact fp32 boundary-band rescue) +
// softmax + V gather + route combine. One 256-thread block per token.
// ============================================================================
__global__ __launch_bounds__(256)
void topk_attend_kernel(const float* __restrict__ q,
                        const float* __restrict__ K0p,
                        const float* __restrict__ K1p,
                        const float* __restrict__ K2p,
                        const float* __restrict__ sal0,
                        const float* __restrict__ sal1,
                        const float* __restrict__ sal2,
                        const float* __restrict__ V0,
                        const float* __restrict__ V1,
                        const float* __restrict__ V2,
                        float* __restrict__ out) {
    const int row = blockIdx.x;
    const int tid = threadIdx.x;
    const int wid = tid >> 5, lane = tid & 31;
    __shared__ unsigned s_u[S0];
    __shared__ unsigned s_hist[256];
    __shared__ float    s_w[64];
    __shared__ int      s_idx[64];
    __shared__ float    s_red[8];
    __shared__ int      s_bin, s_cgt, s_ctie, s_nband;
    __shared__ float    s_m, s_den;
    __shared__ int      s_bidx[16];
    __shared__ float    s_bexact[16];

    const int dynk = g_dynk[row];
    const float* Vp[3]  = {V0, V1, V2};
    const float* Kp[3]  = {K0p, K1p, K2p};
    const float* salp[3]= {sal0, sal1, sal2};
    const int Ss[3] = {S0, S1, S2};
    const float* qrow = q + (size_t)row * DMODEL;

    float4 tot = make_float4(0.f, 0.f, 0.f, 0.f);
    int off = 0;
    for (int l = 0; l < 3; l++) {
        const int S = Ss[l];
        const float* V = Vp[l];

        float lmax = -FLT_MAX;
        for (int i = tid; i < S; i += 256) {
            float v = g_scores[(size_t)row * STOT + off + i];
            lmax = fmaxf(lmax, v);
            s_u[i] = f2key(v);
        }
        #pragma unroll
        for (int o = 16; o; o >>= 1)
            lmax = fmaxf(lmax, __shfl_xor_sync(0xffffffffu, lmax, o));
        if (lane == 0) s_red[wid] = lmax;
        __syncthreads();
        if (tid == 0) {
            float m = s_red[0];
            #pragma unroll
            for (int w = 1; w < 8; w++) m = fmaxf(m, s_red[w]);
            s_m = m;
        }

        unsigned fixedk = 0;
        int kr = dynk;
        for (int p = 3; p >= 0; p--) {
            __syncthreads();
            s_hist[tid] = 0;
            __syncthreads();
            const int sh = p << 3;
            for (int i = tid; i < S; i += 256) {
                unsigned u = s_u[i];
                bool cand = (p == 3) || (((u ^ fixedk) >> (sh + 8)) == 0);
                if (cand) atomicAdd(&s_hist[(u >> sh) & 0xFFu], 1u);
            }
            __syncthreads();
            #pragma unroll
            for (int o = 1; o < 256; o <<= 1) {
                unsigned v = (tid + o < 256) ? s_hist[tid + o] : 0u;
                __syncthreads();
                s_hist[tid] += v;
                __syncthreads();
            }
            if (s_hist[tid] >= (unsigned)kr &&
                (tid == 255 || s_hist[tid + 1] < (unsigned)kr))
                s_bin = tid;
            __syncthreads();
            const int b = s_bin;
            if (b < 255) kr -= (int)s_hist[b + 1];
            fixedk |= (unsigned)b << sh;
        }
        const unsigned T = fixedk;

        const float vb = key2f(T);
        const unsigned klo = f2key(vb - BAND_EPS);
        const unsigned khi = f2key(vb + BAND_EPS);
        if (tid == 0) s_nband = 0;
        __syncthreads();
        for (int i = tid; i < S; i += 256) {
            unsigned u = s_u[i];
            if (u >= klo && u <= khi) {
                int p = atomicAdd(&s_nband, 1);
                if (p < 16) s_bidx[p] = i;
            }
        }
        __syncthreads();
        const int nband = s_nband;

        if (nband <= 1 || nband > 16) {
            if (tid == 0) { s_cgt = 0; s_ctie = 0; }
            __syncthreads();
            const int tie_base = dynk - kr;
            for (int i = tid; i < S; i += 256) {
                unsigned u = s_u[i];
                if (u > T) {
                    int pos = atomicAdd(&s_cgt, 1);
                    s_idx[pos] = i; s_w[pos] = key2f(u);
                } else if (u == T) {
                    int p = atomicAdd(&s_ctie, 1);
                    if (p < kr) { s_idx[tie_base + p] = i; s_w[tie_base + p] = key2f(u); }
                }
            }
            __syncthreads();
        } else {
            if (tid == 0) s_cgt = 0;
            __syncthreads();
            for (int i = tid; i < S; i += 256) {
                unsigned u = s_u[i];
                if (u > khi) {
                    int pos = atomicAdd(&s_cgt, 1);
                    s_idx[pos] = i; s_w[pos] = key2f(u);
                }
            }
            __syncthreads();
            const int n_above = s_cgt;
            const int need = dynk - n_above;
            const float* Kb = Kp[l];
            const float* sl = salp[l];
            for (int j = wid; j < nband; j += 8) {
                const float* kr_ = Kb + (size_t)s_bidx[j] * DMODEL;
                float acc = 0.f;
                for (int d = lane; d < DMODEL; d += 32)
                    acc += qrow[d] * kr_[d];
                #pragma unroll
                for (int o = 16; o; o >>= 1)
                    acc += __shfl_xor_sync(0xffffffffu, acc, o);
                if (lane == 0)
                    s_bexact[j] = acc * 0.03125f + sl[s_bidx[j]];
            }
            __syncthreads();
            if (tid == 0) {
                bool used[16];
                for (int j = 0; j < nband; j++) used[j] = false;
                for (int t = 0; t < need && t < nband; t++) {
                    float best = -FLT_MAX; int bj = 0;
                    for (int j = 0; j < nband; j++)
                        if (!used[j] && s_bexact[j] > best) { best = s_bexact[j]; bj = j; }
                    used[bj] = true;
                    s_idx[n_above + t] = s_bidx[bj];
                    s_w[n_above + t] = key2f(s_u[s_bidx[bj]]);
                }
            }
            __syncthreads();
        }

        const float m = s_m;
        if (tid < 64)
            s_w[tid] = (tid < dynk) ? expf(s_w[tid] - m) : 0.f;
        __syncthreads();
        if (tid < 32) {
            float d = s_w[tid] + s_w[tid + 32];
            #pragma unroll
            for (int o = 16; o; o >>= 1)
                d += __shfl_xor_sync(0xffffffffu, d, o);
            if (tid == 0) s_den = d;
        }
        __syncthreads();

        float4 acc = make_float4(0.f, 0.f, 0.f, 0.f);
        const float4* V4 = (const float4*)V;
        #pragma unroll 4
        for (int k = 0; k < dynk; k++) {
            const float w = s_w[k];
            const float4 v = V4[(size_t)s_idx[k] * 256 + tid];
            acc.x += w * v.x; acc.y += w * v.y;
            acc.z += w * v.z; acc.w += w * v.w;
        }
        const float rw = g_route[row * 3 + l] / s_den;
        tot.x += rw * acc.x; tot.y += rw * acc.y;
        tot.z += rw * acc.z; tot.w += rw * acc.w;
        off += S;
        __syncthreads();
    }
    ((float4*)out)[(size_t)row * 256 + tid] = tot;
}

// ============================================================================
extern "C" void kernel_launch(void* const* d_in, const int* in_sizes, int n_in,
                              void* d_out, int out_size) {
    const float* q    = (const float*)d_in[0];
    const float* K0   = (const float*)d_in[1];
    const float* V0   = (const float*)d_in[2];
    const float* sal0 = (const float*)d_in[3];
    const float* K1   = (const float*)d_in[4];
    const float* V1   = (const float*)d_in[5];
    const float* sal1 = (const float*)d_in[6];
    const float* K2   = (const float*)d_in[7];
    const float* V2   = (const float*)d_in[8];
    const float* sal2 = (const float*)d_in[9];
    const float* rW1  = (const float*)d_in[10];
    const float* rb1  = (const float*)d_in[11];
    const float* rW2  = (const float*)d_in[12];
    const float* rb2  = (const float*)d_in[13];
    const float* pW1  = (const float*)d_in[14];
    const float* pb1  = (const float*)d_in[15];
    const float* pW2  = (const float*)d_in[16];
    const float* pb2  = (const float*)d_in[17];
    float* out = (float*)d_out;

    split_q_kernel<<<BT * 512 / 256, 256>>>(q);
    split_k_kernel<<<STOT * 512 / 256, 256>>>(K0, K1, K2);
    split_w1_kernel<<<DMODEL * 512 / 256, 256>>>(rW1);
    scores_mma_kernel<<<dim3(28, BT / 128), 128>>>(sal0, sal1, sal2);
    gemm_h_mma_kernel<<<dim3(DMODEL / 128, BT / 128), 128>>>(rb1);
    route_kernel<<<BT / 8, 256>>>(rW2, rb2);
    pred_kernel<<<BT / 16, 1024>>>(q, pW1, pb1, pW2, pb2);
    topk_attend_kernel<<<BT, 256>>>(q, K0, K1, K2, sal0, sal1, sal2,
                                    V0, V1, V2, out);
}

// round 14
// speedup vs baseline: 1.2777x; 1.2777x over previous
#include <cuda_runtime.h>
#include <cuda_bf16.h>
#include <math.h>
#include <float.h>

#define BT 2048
#define DMODEL 1024
#define S0 2048
#define S1 1024
#define S2 512
#define STOT 3584
#define KSPLIT 3072   // A:[hi|lo|hi]  B:[hi|hi|lo]
#define BAND_EPS 1e-5f

// ---- static device scratch (no allocation allowed) ----
__device__ float g_h[BT * DMODEL];
__device__ float g_scores[BT * STOT];
__device__ float g_route[BT * 3];
__device__ int   g_dynk[BT];
__device__ __nv_bfloat16 g_A2[(size_t)BT * KSPLIT];     // split q (shared by both GEMMs)
__device__ __nv_bfloat16 g_B2[(size_t)STOT * KSPLIT];   // split K banks
__device__ __nv_bfloat16 g_B2h[(size_t)DMODEL * KSPLIT];// split rW1^T

__device__ __forceinline__ float gelu_erf(float x) {
    return 0.5f * x * (1.0f + erff(x * 0.70710678118654752f));
}
__device__ __forceinline__ unsigned f2key(float f) {
    unsigned b = __float_as_uint(f);
    return (b & 0x80000000u) ? ~b : (b | 0x80000000u);
}
__device__ __forceinline__ float key2f(unsigned u) {
    unsigned b = (u & 0x80000000u) ? (u ^ 0x80000000u) : ~u;
    return __uint_as_float(b);
}

// ============================================================================
// Split kernels: fp32 -> (hi, lo) bf16 along K for 3-product GEMM.
// ============================================================================
__global__ void split_q_kernel(const float* __restrict__ q) {
    int p = blockIdx.x * 256 + threadIdx.x;
    int m = p >> 9, j = p & 511;
    float2 v = *(const float2*)&q[((size_t)m << 10) + (j << 1)];
    __nv_bfloat16 h0 = __float2bfloat16(v.x);
    __nv_bfloat16 h1 = __float2bfloat16(v.y);
    __nv_bfloat16 l0 = __float2bfloat16(v.x - __bfloat162float(h0));
    __nv_bfloat16 l1 = __float2bfloat16(v.y - __bfloat162float(h1));
    __nv_bfloat162 hh; hh.x = h0; hh.y = h1;
    __nv_bfloat162 ll; ll.x = l0; ll.y = l1;
    size_t base = (size_t)m * KSPLIT + (j << 1);
    *(__nv_bfloat162*)&g_A2[base       ] = hh;   // hi
    *(__nv_bfloat162*)&g_A2[base + 1024] = ll;   // lo
    *(__nv_bfloat162*)&g_A2[base + 2048] = hh;   // hi
}

__global__ void split_k_kernel(const float* __restrict__ K0p,
                               const float* __restrict__ K1p,
                               const float* __restrict__ K2p) {
    int p = blockIdx.x * 256 + threadIdx.x;
    int s = p >> 9, j = p & 511;
    const float* src;
    int r;
    if (s < S0)           { src = K0p; r = s; }
    else if (s < S0 + S1) { src = K1p; r = s - S0; }
    else                  { src = K2p; r = s - S0 - S1; }
    float2 v = *(const float2*)&src[((size_t)r << 10) + (j << 1)];
    __nv_bfloat16 h0 = __float2bfloat16(v.x);
    __nv_bfloat16 h1 = __float2bfloat16(v.y);
    __nv_bfloat16 l0 = __float2bfloat16(v.x - __bfloat162float(h0));
    __nv_bfloat16 l1 = __float2bfloat16(v.y - __bfloat162float(h1));
    __nv_bfloat162 hh; hh.x = h0; hh.y = h1;
    __nv_bfloat162 ll; ll.x = l0; ll.y = l1;
    size_t base = (size_t)s * KSPLIT + (j << 1);
    *(__nv_bfloat162*)&g_B2[base       ] = hh;   // hi
    *(__nv_bfloat162*)&g_B2[base + 1024] = hh;   // hi
    *(__nv_bfloat162*)&g_B2[base + 2048] = ll;   // lo
}

// Transposing split of rW1: g_B2h[n][k-split] from rW1[k][n].
__global__ void split_w1_kernel(const float* __restrict__ rW1) {
    int p = blockIdx.x * 256 + threadIdx.x;
    int n  = p & 1023;
    int kp = p >> 10;
    float v0 = rW1[(size_t)(2 * kp    ) * DMODEL + n];
    float v1 = rW1[(size_t)(2 * kp + 1) * DMODEL + n];
    __nv_bfloat16 h0 = __float2bfloat16(v0);
    __nv_bfloat16 h1 = __float2bfloat16(v1);
    __nv_bfloat16 l0 = __float2bfloat16(v0 - __bfloat162float(h0));
    __nv_bfloat16 l1 = __float2bfloat16(v1 - __bfloat162float(h1));
    __nv_bfloat162 hh; hh.x = h0; hh.y = h1;
    __nv_bfloat162 ll; ll.x = l0; ll.y = l1;
    size_t base = (size_t)n * KSPLIT + (kp << 1);
    *(__nv_bfloat162*)&g_B2h[base       ] = hh;  // hi
    *(__nv_bfloat162*)&g_B2h[base + 1024] = hh;  // hi
    *(__nv_bfloat162*)&g_B2h[base + 2048] = ll;  // lo
}

// ============================================================================
// bf16 HMMA GEMM core. 128x128 block tile, K-chunk 32, 8 warps (2x4),
// warp tile 64x32 (R12-validated), ldmatrix fetch, cp.async double buffer.
// ============================================================================
#define LDAS 40
#define STAGE_ELEMS (128 * LDAS)          // one matrix (As or Bs), bf16 elems
#define STAGE_BYTES (STAGE_ELEMS * 2)

__device__ __forceinline__ void mma16816(float* c, const unsigned* a, const unsigned* b) {
    asm volatile(
        "mma.sync.aligned.m16n8k16.row.col.f32.bf16.bf16.f32 "
        "{%0,%1,%2,%3}, {%4,%5,%6,%7}, {%8,%9}, {%0,%1,%2,%3};\n"
        : "+f"(c[0]), "+f"(c[1]), "+f"(c[2]), "+f"(c[3])
        : "r"(a[0]), "r"(a[1]), "r"(a[2]), "r"(a[3]), "r"(b[0]), "r"(b[1]));
}

__device__ __forceinline__ void ldmx4(unsigned& r0, unsigned& r1,
                                      unsigned& r2, unsigned& r3, unsigned addr) {
    asm volatile(
        "ldmatrix.sync.aligned.m8n8.x4.shared.b16 {%0,%1,%2,%3}, [%4];\n"
        : "=r"(r0), "=r"(r1), "=r"(r2), "=r"(r3) : "r"(addr));
}

__device__ __forceinline__ void cpasync16(unsigned dst, const void* src) {
    asm volatile("cp.async.cg.shared.global [%0], [%1], 16;\n"
                 :: "r"(dst), "l"(src));
}

// Shared mainloop: fills c[4][4][4] from g_A2 row-block m0 and Bsrc row-block n0.
// smem layout: [As stage0][Bs stage0][As stage1][Bs stage1]
__device__ __forceinline__ void mma_mainloop(const __nv_bfloat16* __restrict__ Bsrc,
                                             int m0, int n0, int tid,
                                             __nv_bfloat16* sm,
                                             float c[4][4][4]) {
    const int wid = tid >> 5, lane = tid & 31;
    const int warp_m = wid >> 2;
    const int warp_n = wid & 3;
    const int lrow = tid >> 2;              // loader row 0..63 (and +64)
    const int lseg = (tid & 3) << 3;        // 8-elem segment

    const __nv_bfloat16* Aptr = g_A2 + (size_t)(m0 + lrow) * KSPLIT + lseg;
    const __nv_bfloat16* Bptr = Bsrc + (size_t)(n0 + lrow) * KSPLIT + lseg;

    const unsigned smBase = (unsigned)__cvta_generic_to_shared(sm);
    const unsigned wOff = (unsigned)((lrow * LDAS + lseg) * 2);  // write byte off in As

    // ldmatrix lane address components (validated mapping, R12):
    const int rowA = warp_m * 64 + (lane & 15);
    const int colA = (lane >> 4) << 3;
    const int rowB = warp_n * 32 + ((lane >> 4) << 3) + (lane & 7);
    const int colB = ((lane >> 3) & 1) << 3;
    const unsigned aOffBase = (unsigned)((rowA * LDAS + colA) * 2);
    const unsigned bOffBase = (unsigned)((rowB * LDAS + colB) * 2);

    // issue tile kt into stage s
    auto issue = [&](int kt, int s) {
        const int ko = kt * 32;
        const unsigned sb = smBase + (unsigned)(s * 2 * STAGE_BYTES);
        cpasync16(sb + wOff, Aptr + ko);
        cpasync16(sb + wOff + (unsigned)(64 * LDAS * 2), Aptr + (size_t)64 * KSPLIT + ko);
        cpasync16(sb + STAGE_BYTES + wOff, Bptr + ko);
        cpasync16(sb + STAGE_BYTES + wOff + (unsigned)(64 * LDAS * 2),
                  Bptr + (size_t)64 * KSPLIT + ko);
        asm volatile("cp.async.commit_group;\n");
    };

    const int NT = KSPLIT / 32;
    issue(0, 0);
    for (int kt = 0; kt < NT; kt++) {
        if (kt + 1 < NT) {
            issue(kt + 1, (kt + 1) & 1);
            asm volatile("cp.async.wait_group 1;\n");
        } else {
            asm volatile("cp.async.wait_group 0;\n");
        }
        __syncthreads();
        const unsigned sb = smBase + (unsigned)((kt & 1) * 2 * STAGE_BYTES);
        #pragma unroll
        for (int ks = 0; ks < 2; ks++) {
            unsigned a[4][4], b[4][2];
            const unsigned aaddr = sb + aOffBase + (unsigned)(ks * 32);
            #pragma unroll
            for (int mi = 0; mi < 4; mi++)
                ldmx4(a[mi][0], a[mi][1], a[mi][2], a[mi][3],
                      aaddr + (unsigned)(mi * 16 * LDAS * 2));
            const unsigned baddr = sb + STAGE_BYTES + bOffBase + (unsigned)(ks * 32);
            ldmx4(b[0][0], b[0][1], b[1][0], b[1][1], baddr);
            ldmx4(b[2][0], b[2][1], b[3][0], b[3][1],
                  baddr + (unsigned)(16 * LDAS * 2));
            #pragma unroll
            for (int mi = 0; mi < 4; mi++)
                #pragma unroll
                for (int ni = 0; ni < 4; ni++)
                    mma16816(c[mi][ni], a[mi], b[ni]);
        }
        __syncthreads();
    }
}

// ---- scores: g_scores = (A2 @ B2^T)*scale + sal ----
__global__ __launch_bounds__(256, 2)
void scores_mma_kernel(const float* __restrict__ sal0,
                       const float* __restrict__ sal1,
                       const float* __restrict__ sal2) {
    __shared__ __nv_bfloat16 sm[4 * STAGE_ELEMS];   // 40 KB, 2 stages
    const int tid = threadIdx.x;
    const int wid = tid >> 5, lane = tid & 31;
    const int grp = lane >> 2, thr = lane & 3;
    const int warp_m = wid >> 2, warp_n = wid & 3;
    const int m0 = blockIdx.y * 128;
    const int nt = blockIdx.x;

    float c[4][4][4] = {};
    mma_mainloop(g_B2, m0, nt * 128, tid, sm, c);

    const float scale = 0.03125f;
    const float* salp; int sbase;
    if (nt < 16)      { salp = sal0; sbase = 0; }
    else if (nt < 24) { salp = sal1; sbase = S0; }
    else              { salp = sal2; sbase = S0 + S1; }

    #pragma unroll
    for (int mi = 0; mi < 4; mi++) {
        const int r = m0 + warp_m * 64 + mi * 16 + grp;
        #pragma unroll
        for (int ni = 0; ni < 4; ni++) {
            const int cc = nt * 128 + warp_n * 32 + ni * 8 + thr * 2;
            const float s0 = salp[cc - sbase];
            const float s1 = salp[cc + 1 - sbase];
            float2 w0, w1;
            w0.x = c[mi][ni][0] * scale + s0;
            w0.y = c[mi][ni][1] * scale + s1;
            w1.x = c[mi][ni][2] * scale + s0;
            w1.y = c[mi][ni][3] * scale + s1;
            *(float2*)&g_scores[(size_t)r * STOT + cc] = w0;
            *(float2*)&g_scores[(size_t)(r + 8) * STOT + cc] = w1;
        }
    }
}

// ---- hidden: g_h = gelu(A2 @ B2h^T + rb1) ----
__global__ __launch_bounds__(256, 2)
void gemm_h_mma_kernel(const float* __restrict__ bias) {
    __shared__ __nv_bfloat16 sm[4 * STAGE_ELEMS];
    const int tid = threadIdx.x;
    const int wid = tid >> 5, lane = tid & 31;
    const int grp = lane >> 2, thr = lane & 3;
    const int warp_m = wid >> 2, warp_n = wid & 3;
    const int m0 = blockIdx.y * 128;
    const int n0 = blockIdx.x * 128;

    float c[4][4][4] = {};
    mma_mainloop(g_B2h, m0, n0, tid, sm, c);

    #pragma unroll
    for (int mi = 0; mi < 4; mi++) {
        const int r = m0 + warp_m * 64 + mi * 16 + grp;
        #pragma unroll
        for (int ni = 0; ni < 4; ni++) {
            const int cc = n0 + warp_n * 32 + ni * 8 + thr * 2;
            const float b0 = bias[cc], b1 = bias[cc + 1];
            float2 w0, w1;
            w0.x = gelu_erf(c[mi][ni][0] + b0);
            w0.y = gelu_erf(c[mi][ni][1] + b1);
            w1.x = gelu_erf(c[mi][ni][2] + b0);
            w1.y = gelu_erf(c[mi][ni][3] + b1);
            *(float2*)&g_h[(size_t)r * DMODEL + cc] = w0;
            *(float2*)&g_h[(size_t)(r + 8) * DMODEL + cc] = w1;
        }
    }
}

// ============================================================================
// Route softmax (warp/row) and dyn_k predictor (16 rows/block).
// ============================================================================
__global__ void route_kernel(const float* __restrict__ rW2,
                             const float* __restrict__ rb2) {
    const int row = blockIdx.x * 8 + (threadIdx.x >> 5);
    const int lane = threadIdx.x & 31;
    const float* h = &g_h[(size_t)row * DMODEL];
    float a0 = 0.f, a1 = 0.f, a2 = 0.f;
    for (int d = lane; d < DMODEL; d += 32) {
        float hv = h[d];
        a0 += hv * rW2[d * 3 + 0];
        a1 += hv * rW2[d * 3 + 1];
        a2 += hv * rW2[d * 3 + 2];
    }
    #pragma unroll
    for (int o = 16; o; o >>= 1) {
        a0 += __shfl_xor_sync(0xffffffffu, a0, o);
        a1 += __shfl_xor_sync(0xffffffffu, a1, o);
        a2 += __shfl_xor_sync(0xffffffffu, a2, o);
    }
    if (lane == 0) {
        a0 += rb2[0]; a1 += rb2[1]; a2 += rb2[2];
        float m = fmaxf(a0, fmaxf(a1, a2));
        float e0 = expf(a0 - m), e1 = expf(a1 - m), e2 = expf(a2 - m);
        float inv = 1.0f / (e0 + e1 + e2);
        g_route[row * 3 + 0] = e0 * inv;
        g_route[row * 3 + 1] = e1 * inv;
        g_route[row * 3 + 2] = e2 * inv;
    }
}

__global__ __launch_bounds__(1024)
void pred_kernel(const float* __restrict__ q,
                 const float* __restrict__ pW1,
                 const float* __restrict__ pb1,
                 const float* __restrict__ pW2,
                 const float* __restrict__ pb2) {
    const int tid = threadIdx.x;
    const int r = tid >> 6;
    const int j = tid & 63;
    const int lane = tid & 31;
    const int w = tid >> 5, half = w & 1;
    const int row = blockIdx.x * 16 + r;
    __shared__ float s_part[16][2];

    const float* qr = &q[(size_t)row * DMODEL];
    float acc = 0.f;
    #pragma unroll 8
    for (int d = 0; d < DMODEL; d++)
        acc += qr[d] * pW1[d * 64 + j];
    float val = gelu_erf(acc + pb1[j]) * pW2[j];
    #pragma unroll
    for (int o = 16; o; o >>= 1)
        val += __shfl_xor_sync(0xffffffffu, val, o);
    if (lane == 0) s_part[w >> 1][half] = val;
    __syncthreads();
    if (tid < 16) {
        float s = s_part[tid][0] + s_part[tid][1] + pb2[0];
        float sig = 1.0f / (1.0f + expf(-s));
        int k = (int)floorf(sig * 64.0f);
        g_dynk[blockIdx.x * 16 + tid] = max(1, min(64, k));
    }
}

// ============================================================================
// Fused top-dyn_k (radix select + exact fp32 boundary-band rescue) +
// softmax + V gather + route combine. One 256-thread block per token.
// ============================================================================
__global__ __launch_bounds__(256)
void topk_attend_kernel(const float* __restrict__ q,
                        const float* __restrict__ K0p,
                        const float* __restrict__ K1p,
                        const float* __restrict__ K2p,
                        const float* __restrict__ sal0,
                        const float* __restrict__ sal1,
                        const float* __restrict__ sal2,
                        const float* __restrict__ V0,
                        const float* __restrict__ V1,
                        const float* __restrict__ V2,
                        float* __restrict__ out) {
    const int row = blockIdx.x;
    const int tid = threadIdx.x;
    const int wid = tid >> 5, lane = tid & 31;
    __shared__ unsigned s_u[S0];
    __shared__ unsigned s_hist[256];
    __shared__ float    s_w[64];
    __shared__ int      s_idx[64];
    __shared__ float    s_red[8];
    __shared__ int      s_bin, s_cgt, s_ctie, s_nband;
    __shared__ float    s_m, s_den;
    __shared__ int      s_bidx[16];
    __shared__ float    s_bexact[16];

    const int dynk = g_dynk[row];
    const float* Vp[3]  = {V0, V1, V2};
    const float* Kp[3]  = {K0p, K1p, K2p};
    const float* salp[3]= {sal0, sal1, sal2};
    const int Ss[3] = {S0, S1, S2};
    const float* qrow = q + (size_t)row * DMODEL;

    float4 tot = make_float4(0.f, 0.f, 0.f, 0.f);
    int off = 0;
    for (int l = 0; l < 3; l++) {
        const int S = Ss[l];
        const float* V = Vp[l];

        float lmax = -FLT_MAX;
        for (int i = tid; i < S; i += 256) {
            float v = g_scores[(size_t)row * STOT + off + i];
            lmax = fmaxf(lmax, v);
            s_u[i] = f2key(v);
        }
        #pragma unroll
        for (int o = 16; o; o >>= 1)
            lmax = fmaxf(lmax, __shfl_xor_sync(0xffffffffu, lmax, o));
        if (lane == 0) s_red[wid] = lmax;
        __syncthreads();
        if (tid == 0) {
            float m = s_red[0];
            #pragma unroll
            for (int w = 1; w < 8; w++) m = fmaxf(m, s_red[w]);
            s_m = m;
        }

        unsigned fixedk = 0;
        int kr = dynk;
        for (int p = 3; p >= 0; p--) {
            __syncthreads();
            s_hist[tid] = 0;
            __syncthreads();
            const int sh = p << 3;
            for (int i = tid; i < S; i += 256) {
                unsigned u = s_u[i];
                bool cand = (p == 3) || (((u ^ fixedk) >> (sh + 8)) == 0);
                if (cand) atomicAdd(&s_hist[(u >> sh) & 0xFFu], 1u);
            }
            __syncthreads();
            #pragma unroll
            for (int o = 1; o < 256; o <<= 1) {
                unsigned v = (tid + o < 256) ? s_hist[tid + o] : 0u;
                __syncthreads();
                s_hist[tid] += v;
                __syncthreads();
            }
            if (s_hist[tid] >= (unsigned)kr &&
                (tid == 255 || s_hist[tid + 1] < (unsigned)kr))
                s_bin = tid;
            __syncthreads();
            const int b = s_bin;
            if (b < 255) kr -= (int)s_hist[b + 1];
            fixedk |= (unsigned)b << sh;
        }
        const unsigned T = fixedk;

        const float vb = key2f(T);
        const unsigned klo = f2key(vb - BAND_EPS);
        const unsigned khi = f2key(vb + BAND_EPS);
        if (tid == 0) s_nband = 0;
        __syncthreads();
        for (int i = tid; i < S; i += 256) {
            unsigned u = s_u[i];
            if (u >= klo && u <= khi) {
                int p = atomicAdd(&s_nband, 1);
                if (p < 16) s_bidx[p] = i;
            }
        }
        __syncthreads();
        const int nband = s_nband;

        if (nband <= 1 || nband > 16) {
            if (tid == 0) { s_cgt = 0; s_ctie = 0; }
            __syncthreads();
            const int tie_base = dynk - kr;
            for (int i = tid; i < S; i += 256) {
                unsigned u = s_u[i];
                if (u > T) {
                    int pos = atomicAdd(&s_cgt, 1);
                    s_idx[pos] = i; s_w[pos] = key2f(u);
                } else if (u == T) {
                    int p = atomicAdd(&s_ctie, 1);
                    if (p < kr) { s_idx[tie_base + p] = i; s_w[tie_base + p] = key2f(u); }
                }
            }
            __syncthreads();
        } else {
            if (tid == 0) s_cgt = 0;
            __syncthreads();
            for (int i = tid; i < S; i += 256) {
                unsigned u = s_u[i];
                if (u > khi) {
                    int pos = atomicAdd(&s_cgt, 1);
                    s_idx[pos] = i; s_w[pos] = key2f(u);
                }
            }
            __syncthreads();
            const int n_above = s_cgt;
            const int need = dynk - n_above;
            const float* Kb = Kp[l];
            const float* sl = salp[l];
            for (int j = wid; j < nband; j += 8) {
                const float* kr_ = Kb + (size_t)s_bidx[j] * DMODEL;
                float acc = 0.f;
                for (int d = lane; d < DMODEL; d += 32)
                    acc += qrow[d] * kr_[d];
                #pragma unroll
                for (int o = 16; o; o >>= 1)
                    acc += __shfl_xor_sync(0xffffffffu, acc, o);
                if (lane == 0)
                    s_bexact[j] = acc * 0.03125f + sl[s_bidx[j]];
            }
            __syncthreads();
            if (tid == 0) {
                bool used[16];
                for (int j = 0; j < nband; j++) used[j] = false;
                for (int t = 0; t < need && t < nband; t++) {
                    float best = -FLT_MAX; int bj = 0;
                    for (int j = 0; j < nband; j++)
                        if (!used[j] && s_bexact[j] > best) { best = s_bexact[j]; bj = j; }
                    used[bj] = true;
                    s_idx[n_above + t] = s_bidx[bj];
                    s_w[n_above + t] = key2f(s_u[s_bidx[bj]]);
                }
            }
            __syncthreads();
        }

        const float m = s_m;
        if (tid < 64)
            s_w[tid] = (tid < dynk) ? expf(s_w[tid] - m) : 0.f;
        __syncthreads();
        if (tid < 32) {
            float d = s_w[tid] + s_w[tid + 32];
            #pragma unroll
            for (int o = 16; o; o >>= 1)
                d += __shfl_xor_sync(0xffffffffu, d, o);
            if (tid == 0) s_den = d;
        }
        __syncthreads();

        float4 acc = make_float4(0.f, 0.f, 0.f, 0.f);
        const float4* V4 = (const float4*)V;
        #pragma unroll 4
        for (int k = 0; k < dynk; k++) {
            const float w = s_w[k];
            const float4 v = V4[(size_t)s_idx[k] * 256 + tid];
            acc.x += w * v.x; acc.y += w * v.y;
            acc.z += w * v.z; acc.w += w * v.w;
        }
        const float rw = g_route[row * 3 + l] / s_den;
        tot.x += rw * acc.x; tot.y += rw * acc.y;
        tot.z += rw * acc.z; tot.w += rw * acc.w;
        off += S;
        __syncthreads();
    }
    ((float4*)out)[(size_t)row * 256 + tid] = tot;
}

// ============================================================================
extern "C" void kernel_launch(void* const* d_in, const int* in_sizes, int n_in,
                              void* d_out, int out_size) {
    const float* q    = (const float*)d_in[0];
    const float* K0   = (const float*)d_in[1];
    const float* V0   = (const float*)d_in[2];
    const float* sal0 = (const float*)d_in[3];
    const float* K1   = (const float*)d_in[4];
    const float* V1   = (const float*)d_in[5];
    const float* sal1 = (const float*)d_in[6];
    const float* K2   = (const float*)d_in[7];
    const float* V2   = (const float*)d_in[8];
    const float* sal2 = (const float*)d_in[9];
    const float* rW1  = (const float*)d_in[10];
    const float* rb1  = (const float*)d_in[11];
    const float* rW2  = (const float*)d_in[12];
    const float* rb2  = (const float*)d_in[13];
    const float* pW1  = (const float*)d_in[14];
    const float* pb1  = (const float*)d_in[15];
    const float* pW2  = (const float*)d_in[16];
    const float* pb2  = (const float*)d_in[17];
    float* out = (float*)d_out;

    split_q_kernel<<<BT * 512 / 256, 256>>>(q);
    split_k_kernel<<<STOT * 512 / 256, 256>>>(K0, K1, K2);
    split_w1_kernel<<<DMODEL * 512 / 256, 256>>>(rW1);
    scores_mma_kernel<<<dim3(28, BT / 128), 256>>>(sal0, sal1, sal2);
    gemm_h_mma_kernel<<<dim3(DMODEL / 128, BT / 128), 256>>>(rb1);
    route_kernel<<<BT / 8, 256>>>(rW2, rb2);
    pred_kernel<<<BT / 16, 1024>>>(q, pW1, pb1, pW2, pb2);
    topk_attend_kernel<<<BT, 256>>>(q, K0, K1, K2, sal0, sal1, sal2,
                                    V0, V1, V2, out);
}